// round 10
// baseline (speedup 1.0000x reference)
#include <cuda_runtime.h>
#include <cuda_fp16.h>
#include <math.h>
#include <cstdint>

// Problem constants
#define Bn  4
#define Cc  256
#define C8  32
#define HH  64
#define WW  64
#define HW  4096
#define CHW (Cc*HW)
#define TOT (Bn*CHW)

// ---------------- scratch (__device__ globals) ------------------------------
__device__ float g_mean1[Bn*HW];
__device__ float g_max1 [Bn*HW];
__device__ float g_mean2[Bn*HW];
__device__ float g_max2 [Bn*HW];
__device__ float g_gate1[Bn*HW];
__device__ float g_gate2[Bn*HW];
__device__ __align__(16) __half g_x1h[(size_t)Bn*CHW];     // [B][C][HW] fp16 gated x1
__device__ __align__(16) __half g_x2h[(size_t)Bn*CHW];     // [B][C][HW] fp16 gated x2
__device__ __align__(16) __half g_Wq[C8*Cc];
__device__ __align__(16) __half g_Wk[C8*Cc];
__device__ __align__(16) __half g_Wv[Cc*Cc];
__device__ __align__(128) __half g_Qh[(size_t)Bn*HW*32];   // [B][N][32]  (pre-scaled by log2e)
__device__ __align__(128) __half g_Kh[(size_t)Bn*HW*32];   // [B][N][32]
__device__ __align__(128) __half g_Vh[(size_t)Bn*HW*256];  // [B][N][256]

// ======================= warp MMA helpers ====================================
__device__ __forceinline__ uint32_t smem_to_u32(const void* p) {
    uint32_t a;
    asm("{ .reg .u64 t; cvta.to.shared.u64 t, %1; cvt.u32.u64 %0, t; }" : "=r"(a) : "l"(p));
    return a;
}
__device__ __forceinline__ void mma16816(float* d, const uint32_t* a, const uint32_t* b) {
    asm volatile("mma.sync.aligned.m16n8k16.row.col.f32.f16.f16.f32 "
                 "{%0,%1,%2,%3}, {%4,%5,%6,%7}, {%8,%9}, {%0,%1,%2,%3};"
                 : "+f"(d[0]), "+f"(d[1]), "+f"(d[2]), "+f"(d[3])
                 : "r"(a[0]), "r"(a[1]), "r"(a[2]), "r"(a[3]), "r"(b[0]), "r"(b[1]));
}
// fp16-accumulate variant: d = {half2 row r, half2 row r+8}
__device__ __forceinline__ void mma16816h(uint32_t* d, const uint32_t* a, const uint32_t* b) {
    asm volatile("mma.sync.aligned.m16n8k16.row.col.f16.f16.f16.f16 "
                 "{%0,%1}, {%2,%3,%4,%5}, {%6,%7}, {%0,%1};"
                 : "+r"(d[0]), "+r"(d[1])
                 : "r"(a[0]), "r"(a[1]), "r"(a[2]), "r"(a[3]), "r"(b[0]), "r"(b[1]));
}
__device__ __forceinline__ void ldsm4(uint32_t* r, uint32_t addr) {
    asm volatile("ldmatrix.sync.aligned.m8n8.x4.shared.b16 {%0,%1,%2,%3}, [%4];"
                 : "=r"(r[0]), "=r"(r[1]), "=r"(r[2]), "=r"(r[3]) : "r"(addr));
}
__device__ __forceinline__ void ldsm4t(uint32_t* r, uint32_t addr) {
    asm volatile("ldmatrix.sync.aligned.m8n8.x4.trans.shared.b16 {%0,%1,%2,%3}, [%4];"
                 : "=r"(r[0]), "=r"(r[1]), "=r"(r[2]), "=r"(r[3]) : "r"(addr));
}
__device__ __forceinline__ void cpa16(uint32_t dst, const void* src) {
    asm volatile("cp.async.cg.shared.global [%0], [%1], 16;" :: "r"(dst), "l"(src) : "memory");
}
#define CP_COMMIT() asm volatile("cp.async.commit_group;" ::: "memory")
#define CP_WAIT0()  asm volatile("cp.async.wait_group 0;" ::: "memory")
#define CP_WAIT1()  asm volatile("cp.async.wait_group 1;" ::: "memory")

__device__ __forceinline__ uint32_t packh2(float a, float b) {
    __half2 h = __float22half2_rn(make_float2(a, b));
    return *reinterpret_cast<uint32_t*>(&h);
}

// ---------------- kernel 1: channel mean & max (both inputs, z-merged) -------
__global__ __launch_bounds__(256) void reduce_kernel(const float* __restrict__ xa,
                                                     const float* __restrict__ xb,
                                                     float* __restrict__ meanA, float* __restrict__ maxA,
                                                     float* __restrict__ meanB, float* __restrict__ maxB) {
    __shared__ float S[4][64], M[4][64];
    const float* x = blockIdx.z ? xb : xa;
    float* meanO = blockIdx.z ? meanB : meanA;
    float* maxO  = blockIdx.z ? maxB  : maxA;
    int nl = threadIdx.x & 63, cg = threadIdx.x >> 6;
    int n = blockIdx.x * 64 + nl;
    int b = blockIdx.y;
    const float* xp = x + (size_t)b * CHW + (size_t)cg * 64 * HW + n;
    float s = 0.f, m = -3.4e38f;
#pragma unroll 8
    for (int i = 0; i < 64; ++i) { float v = xp[(size_t)i * HW]; s += v; m = fmaxf(m, v); }
    S[cg][nl] = s; M[cg][nl] = m;
    __syncthreads();
    if (cg == 0) {
        s = S[0][nl] + S[1][nl] + S[2][nl] + S[3][nl];
        m = fmaxf(fmaxf(M[0][nl], M[1][nl]), fmaxf(M[2][nl], M[3][nl]));
        meanO[b * HW + n] = s * (1.0f / Cc);
        maxO [b * HW + n] = m;
    }
}

// ---------------- kernel 2: 3x3 conv + sigmoid -> gates (z-merged) -----------
__global__ void gate_kernel(const float* __restrict__ meanA, const float* __restrict__ maxA,
                            const float* __restrict__ meanB, const float* __restrict__ maxB,
                            const float* __restrict__ w,
                            float* __restrict__ gateA, float* __restrict__ gateB) {
    const float* meanI = blockIdx.z ? meanB : meanA;
    const float* maxI  = blockIdx.z ? maxB  : maxA;
    float* gate = blockIdx.z ? gateB : gateA;
    int n = blockIdx.x * 256 + threadIdx.x;
    int b = blockIdx.y;
    int h = n >> 6, ww2 = n & 63;
    float a = 0.f;
#pragma unroll
    for (int dh = -1; dh <= 1; ++dh) {
        int hh = h + dh; if (hh < 0 || hh >= HH) continue;
#pragma unroll
        for (int dw = -1; dw <= 1; ++dw) {
            int wv = ww2 + dw; if (wv < 0 || wv >= WW) continue;
            int idx = b * HW + hh * WW + wv;
            int kid = (dh + 1) * 3 + (dw + 1);
            a += meanI[idx] * __ldg(&w[kid]) + maxI[idx] * __ldg(&w[9 + kid]);
        }
    }
    gate[b * HW + n] = 1.f / (1.f + __expf(-a));
}

// ---------------- kernel 3: weight fp32 -> fp16 conversion -------------------
__global__ void wcvt_kernel(const float* __restrict__ qw, const float* __restrict__ kw,
                            const float* __restrict__ vw,
                            __half* __restrict__ whq, __half* __restrict__ whk,
                            __half* __restrict__ whv) {
    int i = blockIdx.x * 256 + threadIdx.x;
    if (i < 8192)        whq[i] = __float2half(qw[i]);
    else if (i < 16384)  whk[i - 8192] = __float2half(kw[i - 8192]);
    else                 whv[i - 16384] = __float2half(vw[i - 16384]);
}

// ---------------- kernel 4a: x1h = fp16(x1 * gate1) --------------------------
__global__ __launch_bounds__(256) void ew_x1_kernel(const float* __restrict__ x,
                                                    const float* __restrict__ gate,
                                                    __half* __restrict__ xh) {
    int idx = (blockIdx.x * 256 + threadIdx.x) * 4;
    int b = blockIdx.y;
    int n = idx & (HW - 1);
    float4 xv = *(const float4*)&x[(size_t)b * CHW + idx];
    float4 gv = *(const float4*)&gate[b * HW + n];
    uint2 o;
    o.x = packh2(xv.x * gv.x, xv.y * gv.y);
    o.y = packh2(xv.z * gv.z, xv.w * gv.w);
    *(uint2*)&xh[(size_t)b * CHW + idx] = o;
}

// ---------------- kernel 4b: x2s (fp32 out) + x2h (fp16) ---------------------
__global__ __launch_bounds__(256) void ew_x2_kernel(const float* __restrict__ x,
                                                    const float* __restrict__ gate,
                                                    __half* __restrict__ xh,
                                                    float* __restrict__ xs) {
    int idx = (blockIdx.x * 256 + threadIdx.x) * 4;
    int b = blockIdx.y;
    int n = idx & (HW - 1);
    float4 xv = *(const float4*)&x[(size_t)b * CHW + idx];
    float4 gv = *(const float4*)&gate[b * HW + n];
    float4 r = make_float4(xv.x * gv.x, xv.y * gv.y, xv.z * gv.z, xv.w * gv.w);
    *(float4*)&xs[(size_t)b * CHW + idx] = r;
    uint2 o;
    o.x = packh2(r.x, r.y);
    o.y = packh2(r.z, r.w);
    *(uint2*)&xh[(size_t)b * CHW + idx] = o;
}

// ---------------- kernel 5: mma projection -----------------------------------
#define XBUF  (32 * 136 * 2)             // 8704 bytes per X stage
#define XSTG  (2 * XBUF)                 // 17408

template<int OT, int WMG, int MT>
__global__ __launch_bounds__(256) void proj_mma_kernel(const __half* __restrict__ Xg,
                                                       const __half* __restrict__ Wg,
                                                       const float* __restrict__ bias,
                                                       __half* __restrict__ out,
                                                       int Ototal, float scale) {
    extern __shared__ char smem[];
    __half* Wsm = (__half*)(smem + XSTG);            // [OT][264]
    uint32_t sb = smem_to_u32(smem);

    int t = threadIdx.x, lane = t & 31, w = t >> 5;
    int gr = lane >> 2, gc = lane & 3;
    int n0 = blockIdx.x * 128;
    int o0g = blockIdx.y * OT;
    int b = blockIdx.z;
    int wm0 = (w % WMG) * (MT * 16);
    int wo0 = (w / WMG) * 32;

    const __half* Xb = Xg + (size_t)b * CHW + n0;

#pragma unroll
    for (int it = 0; it < OT / 8; ++it) {
        int lin = it * 256 + t;
        int row = lin >> 5, ch = lin & 31;
        *(uint4*)&Wsm[row * 264 + ch * 8] = *(const uint4*)&Wg[(size_t)(o0g + row) * Cc + ch * 8];
    }

    auto loadX = [&](int ks) {
        const __half* src = Xb + (size_t)(ks * 32) * HW;
        uint32_t dstb = sb + (ks & 1) * XBUF;
#pragma unroll
        for (int it = 0; it < 2; ++it) {
            int lin = it * 256 + t;
            int row = lin >> 4, ch = lin & 15;
            cpa16(dstb + (row * 136 + ch * 8) * 2, src + (size_t)row * HW + ch * 8);
        }
    };

    loadX(0); CP_COMMIT();

    float oacc[MT][4][4];
#pragma unroll
    for (int mt = 0; mt < MT; ++mt)
#pragma unroll
        for (int nt = 0; nt < 4; ++nt)
#pragma unroll
            for (int j = 0; j < 4; ++j) oacc[mt][nt][j] = 0.f;

    for (int ks = 0; ks < 8; ++ks) {
        if (ks < 7) { loadX(ks + 1); CP_COMMIT(); CP_WAIT1(); }
        else        { CP_WAIT0(); }
        __syncthreads();

        uint32_t xbuf = sb + (ks & 1) * XBUF;
#pragma unroll
        for (int kt = 0; kt < 2; ++kt) {
            uint32_t af[MT][4];
#pragma unroll
            for (int mt = 0; mt < MT; ++mt) {
                uint32_t r[4];
                uint32_t addr = xbuf + ((kt * 16 + (lane & 15)) * 136
                                        + wm0 + mt * 16 + ((lane >> 4) << 3)) * 2;
                ldsm4t(r, addr);
                af[mt][0] = r[0]; af[mt][1] = r[2]; af[mt][2] = r[1]; af[mt][3] = r[3];
            }
            int ksk = ks * 32 + kt * 16;
#pragma unroll
            for (int nt = 0; nt < 4; ++nt) {
                uint32_t bf[2];
                bf[0] = *(const uint32_t*)&Wsm[(wo0 + nt * 8 + gr) * 264 + ksk + 2 * gc];
                bf[1] = *(const uint32_t*)&Wsm[(wo0 + nt * 8 + gr) * 264 + ksk + 8 + 2 * gc];
#pragma unroll
                for (int mt = 0; mt < MT; ++mt)
                    mma16816(oacc[mt][nt], af[mt], bf);
            }
        }
        __syncthreads();
    }

    uint32_t* outp = (uint32_t*)out;
    int ostr = Ototal >> 1;
#pragma unroll
    for (int nt = 0; nt < 4; ++nt) {
        int o = o0g + wo0 + nt * 8 + 2 * gc;
        float blo = __ldg(&bias[o]), bhi = __ldg(&bias[o + 1]);
#pragma unroll
        for (int mt = 0; mt < MT; ++mt) {
            int n = n0 + wm0 + mt * 16 + gr;
            outp[((size_t)b * HW + n)     * ostr + (o >> 1)]
                = packh2((oacc[mt][nt][0] + blo) * scale, (oacc[mt][nt][1] + bhi) * scale);
            outp[((size_t)b * HW + n + 8) * ostr + (o >> 1)]
                = packh2((oacc[mt][nt][2] + blo) * scale, (oacc[mt][nt][3] + bhi) * scale);
        }
    }
}

// ---------------- kernel 6: mma.sync fp16 flash attention + residual ---------
// BM=128 q/CTA, 512 thr = 16 warps = 8 qgroups x 2 chgroups.
// 3-stage cp.async pipeline; V + K in SMEM; fp16 accumulators; exp2 softmax.
#define BM 128
#define BN 64
#define NTHR 512
#define NIT (HW / BN)
#define VSTR 264                       // halves per V row
#define VBYT (BN * VSTR * 2)           // 33792
#define KSTR 40                        // halves per K row (64B + 16B pad)
#define KBYT (BN * KSTR * 2)           // 5120
#define SSTR (VBYT + KBYT)             // 38912 per stage
#define FLASH_SMEM (BM * 257 * 4)      // 131584 >= 3*SSTR (116736)

__global__ __launch_bounds__(NTHR, 1) void flash_mma_kernel(
    const __half* __restrict__ Qg, const __half* __restrict__ Kg,
    const __half* __restrict__ Vg,
    const float* __restrict__ x1, const float* __restrict__ gate1,
    const float* __restrict__ gamma,
    float* __restrict__ out) {
    extern __shared__ char smem[];
    uint32_t sbase = smem_to_u32(smem);
    float* Os = (float*)smem;

    int t = threadIdx.x, lane = t & 31, w = t >> 5;
    int qg = w & 7, cg = w >> 3;
    int b = blockIdx.y, m0 = blockIdx.x * BM;
    int r = lane >> 2, c2 = (lane & 3) * 2;

    const __half* Qb = Qg + ((size_t)b * HW + m0 + qg * 16) * 32;
    const __half* Kb = Kg + (size_t)b * HW * 32;
    const __half* Vb = Vg + (size_t)b * HW * 256;

    uint32_t qf[2][4];
#pragma unroll
    for (int kt = 0; kt < 2; ++kt) {
        qf[kt][0] = *(const uint32_t*)&Qb[(r)     * 32 + kt * 16 + c2];
        qf[kt][1] = *(const uint32_t*)&Qb[(r + 8) * 32 + kt * 16 + c2];
        qf[kt][2] = *(const uint32_t*)&Qb[(r)     * 32 + kt * 16 + 8 + c2];
        qf[kt][3] = *(const uint32_t*)&Qb[(r + 8) * 32 + kt * 16 + 8 + c2];
    }

    // stage loader: V (64 keys x 256ch) + K (64 keys x 32ch)
    auto loadStage = [&](int s) {
        uint32_t base = sbase + (s % 3) * SSTR;
        const __half* vsrc = Vb + (size_t)s * BN * 256;
#pragma unroll
        for (int it = 0; it < 4; ++it) {
            int lin = it * NTHR + t;
            int key = lin >> 5, ch16 = lin & 31;
            cpa16(base + key * (VSTR * 2) + ch16 * 16, vsrc + (size_t)key * 256 + ch16 * 8);
        }
        if (t < 256) {
            int row = t >> 2, ch16 = t & 3;
            cpa16(base + VBYT + row * (KSTR * 2) + ch16 * 16,
                  Kb + ((size_t)s * BN + row) * 32 + ch16 * 8);
        }
    };

    // O accumulators: fp16 half2 pairs {row r, row r+8} per (channel-pair, mma)
    uint32_t oacc[16][2];
#pragma unroll
    for (int i = 0; i < 16; ++i) { oacc[i][0] = 0u; oacc[i][1] = 0u; }
    float mrow0 = -3.4e38f, mrow1 = -3.4e38f, lsum0 = 0.f, lsum1 = 0.f;

    loadStage(0); CP_COMMIT();
    loadStage(1); CP_COMMIT();

    int t2 = lane >> 3, rw = lane & 7;   // ldsm K addressing
    for (int i = 0; i < NIT; ++i) {
        if (i < NIT - 2) CP_WAIT1(); else CP_WAIT0();
        __syncthreads();
        if (i + 2 < NIT) { loadStage(i + 2); CP_COMMIT(); }

        uint32_t stg = sbase + (i % 3) * SSTR;
        uint32_t kb = stg + VBYT;

        // ---- S = Q K^T (fp16 acc): 16 q rows x 64 keys ----
        uint32_t sacc[8][2];
#pragma unroll
        for (int nt = 0; nt < 8; ++nt) { sacc[nt][0] = 0u; sacc[nt][1] = 0u; }
#pragma unroll
        for (int kt = 0; kt < 2; ++kt) {
#pragma unroll
            for (int j4 = 0; j4 < 4; ++j4) {
                uint32_t kf[4];
                uint32_t addr = kb + ((j4 * 16 + (t2 >> 1) * 8 + rw) * KSTR
                                      + kt * 16 + (t2 & 1) * 8) * 2;
                ldsm4(kf, addr);
                mma16816h(sacc[2 * j4],     qf[kt], kf);
                mma16816h(sacc[2 * j4 + 1], qf[kt], kf + 2);
            }
        }
        __half2* s2 = reinterpret_cast<__half2*>(sacc);

        // ---- online softmax (base-2, half2 datapath) ----
        __half2 hm0 = s2[0], hm1 = s2[1];
#pragma unroll
        for (int nt = 1; nt < 8; ++nt) {
            hm0 = __hmax2(hm0, s2[2 * nt]);
            hm1 = __hmax2(hm1, s2[2 * nt + 1]);
        }
        float tm0 = fmaxf(__low2float(hm0), __high2float(hm0));
        float tm1 = fmaxf(__low2float(hm1), __high2float(hm1));
        tm0 = fmaxf(tm0, __shfl_xor_sync(0xffffffffu, tm0, 1));
        tm0 = fmaxf(tm0, __shfl_xor_sync(0xffffffffu, tm0, 2));
        tm1 = fmaxf(tm1, __shfl_xor_sync(0xffffffffu, tm1, 1));
        tm1 = fmaxf(tm1, __shfl_xor_sync(0xffffffffu, tm1, 2));
        float mn0 = fmaxf(mrow0, tm0), mn1 = fmaxf(mrow1, tm1);
        float sc0 = exp2f(mrow0 - mn0), sc1 = exp2f(mrow1 - mn1);
        mrow0 = mn0; mrow1 = mn1;

        __half2 mn0h = __float2half2_rn(mn0), mn1h = __float2half2_rn(mn1);
        __half2 rs0h = __float2half2_rn(0.f), rs1h = rs0h;
        uint32_t pf[4][4];
#pragma unroll
        for (int nt = 0; nt < 8; ++nt) {
            __half2 p0 = h2exp2(__hsub2(s2[2 * nt],     mn0h));
            __half2 p1 = h2exp2(__hsub2(s2[2 * nt + 1], mn1h));
            rs0h = __hadd2(rs0h, p0);
            rs1h = __hadd2(rs1h, p1);
            pf[nt >> 1][(nt & 1) * 2 + 0] = *reinterpret_cast<uint32_t*>(&p0);
            pf[nt >> 1][(nt & 1) * 2 + 1] = *reinterpret_cast<uint32_t*>(&p1);
        }
        float rs0 = __low2float(rs0h) + __high2float(rs0h);
        float rs1 = __low2float(rs1h) + __high2float(rs1h);
        rs0 += __shfl_xor_sync(0xffffffffu, rs0, 1);
        rs0 += __shfl_xor_sync(0xffffffffu, rs0, 2);
        rs1 += __shfl_xor_sync(0xffffffffu, rs1, 1);
        rs1 += __shfl_xor_sync(0xffffffffu, rs1, 2);
        lsum0 = lsum0 * sc0 + rs0;
        lsum1 = lsum1 * sc1 + rs1;

        if (__ballot_sync(0xffffffffu, (sc0 < 1.f) || (sc1 < 1.f))) {
            __half2 sc0h = __float2half2_rn(sc0), sc1h = __float2half2_rn(sc1);
            __half2* o2 = reinterpret_cast<__half2*>(oacc);
#pragma unroll
            for (int ct = 0; ct < 16; ++ct) {
                o2[2 * ct]     = __hmul2(o2[2 * ct],     sc0h);
                o2[2 * ct + 1] = __hmul2(o2[2 * ct + 1], sc1h);
            }
        }

        // ---- O += P V (fp16 acc): 128 channels for this warp ----
        uint32_t rowoff = (lane & 15) * (VSTR * 2) + ((lane >> 4) * 8 + cg * 128) * 2;
#pragma unroll
        for (int kt2 = 0; kt2 < 4; ++kt2) {
            uint32_t base = stg + kt2 * 16 * (VSTR * 2) + rowoff;
#pragma unroll
            for (int cp = 0; cp < 8; ++cp) {
                uint32_t vf[4];
                ldsm4t(vf, base + cp * 32);
                mma16816h(oacc[2 * cp],     pf[kt2], vf);
                mma16816h(oacc[2 * cp + 1], pf[kt2], vf + 2);
            }
        }
    }

    // ---- epilogue ----
    __syncthreads();
    float inv0 = 1.0f / lsum0, inv1 = 1.0f / lsum1;
    int row = qg * 16 + r;
    __half2* o2 = reinterpret_cast<__half2*>(oacc);
#pragma unroll
    for (int ct = 0; ct < 16; ++ct) {
        int ch = cg * 128 + ct * 8 + c2;
        float2 lo = __half22float2(o2[2 * ct]);
        float2 hi = __half22float2(o2[2 * ct + 1]);
        Os[row * 257 + ch]           = lo.x * inv0;
        Os[row * 257 + ch + 1]       = lo.y * inv0;
        Os[(row + 8) * 257 + ch]     = hi.x * inv1;
        Os[(row + 8) * 257 + ch + 1] = hi.y * inv1;
    }
    __syncthreads();

    float g = __ldg(gamma);
    int nloc = t & 127, cquad = t >> 7;
    float gg = gate1[b * HW + m0 + nloc];
#pragma unroll 4
    for (int it = 0; it < 64; ++it) {
        int ch = it * 4 + cquad;
        size_t gi = (size_t)b * CHW + (size_t)ch * HW + m0 + nloc;
        out[gi] = g * Os[nloc * 257 + ch] + x1[gi] * gg;
    }
}

// ---------------- launcher ---------------------------------------------------
extern "C" void kernel_launch(void* const* d_in, const int* in_sizes, int n_in,
                              void* d_out, int out_size) {
    const float* x1    = (const float*)d_in[0];
    const float* x2    = (const float*)d_in[1];
    const float* sa_w  = (const float*)d_in[2];
    const float* q_w   = (const float*)d_in[3];
    const float* q_b   = (const float*)d_in[4];
    const float* k_w   = (const float*)d_in[5];
    const float* k_b   = (const float*)d_in[6];
    const float* v_w   = (const float*)d_in[7];
    const float* v_b   = (const float*)d_in[8];
    const float* gamma = (const float*)d_in[9];

    float* out = (float*)d_out;        // out1 at [0, TOT), x2s at [TOT, 2*TOT)
    float* x2s = out + TOT;

    float *p_m1, *p_x1m, *p_m2, *p_x2m, *p_g1, *p_g2;
    __half *p_x1h, *p_x2h, *p_Wq, *p_Wk, *p_Wv, *p_Qh, *p_Kh, *p_Vh;
    cudaGetSymbolAddress((void**)&p_m1,  g_mean1);
    cudaGetSymbolAddress((void**)&p_x1m, g_max1);
    cudaGetSymbolAddress((void**)&p_m2,  g_mean2);
    cudaGetSymbolAddress((void**)&p_x2m, g_max2);
    cudaGetSymbolAddress((void**)&p_g1,  g_gate1);
    cudaGetSymbolAddress((void**)&p_g2,  g_gate2);
    cudaGetSymbolAddress((void**)&p_x1h, g_x1h);
    cudaGetSymbolAddress((void**)&p_x2h, g_x2h);
    cudaGetSymbolAddress((void**)&p_Wq,  g_Wq);
    cudaGetSymbolAddress((void**)&p_Wk,  g_Wk);
    cudaGetSymbolAddress((void**)&p_Wv,  g_Wv);
    cudaGetSymbolAddress((void**)&p_Qh,  g_Qh);
    cudaGetSymbolAddress((void**)&p_Kh,  g_Kh);
    cudaGetSymbolAddress((void**)&p_Vh,  g_Vh);

    const int SM_QK = XSTG + 32 * 264 * 2;    // 34304
    const int SM_V  = XSTG + 128 * 264 * 2;   // 84992
    cudaFuncSetAttribute((const void*)proj_mma_kernel<32, 8, 1>,
                         cudaFuncAttributeMaxDynamicSharedMemorySize, SM_QK);
    cudaFuncSetAttribute((const void*)proj_mma_kernel<128, 2, 4>,
                         cudaFuncAttributeMaxDynamicSharedMemorySize, SM_V);
    cudaFuncSetAttribute(flash_mma_kernel, cudaFuncAttributeMaxDynamicSharedMemorySize, FLASH_SMEM);

    // spatial attention stats + gates (x1/x2 merged via grid.z)
    reduce_kernel<<<dim3(HW / 64, Bn, 2), 256>>>(x1, x2, p_m1, p_x1m, p_m2, p_x2m);
    gate_kernel<<<dim3(HW / 256, Bn, 2), 256>>>(p_m1, p_x1m, p_m2, p_x2m, sa_w, p_g1, p_g2);
    wcvt_kernel<<<320, 256>>>(q_w, k_w, v_w, p_Wq, p_Wk, p_Wv);

    // gated activations (x2s also to output)
    ew_x1_kernel<<<dim3(CHW / 1024, Bn), 256>>>(x1, p_g1, p_x1h);
    ew_x2_kernel<<<dim3(CHW / 1024, Bn), 256>>>(x2, p_g2, p_x2h, x2s);

    // projections (tensor core); Q pre-scaled by log2e for base-2 softmax
    const float LOG2E = 1.4426950408889634f;
    proj_mma_kernel<32, 8, 1><<<dim3(HW / 128, 1, Bn), 256, SM_QK>>>(p_x1h, p_Wq, q_b, p_Qh, 32, LOG2E);
    proj_mma_kernel<32, 8, 1><<<dim3(HW / 128, 1, Bn), 256, SM_QK>>>(p_x2h, p_Wk, k_b, p_Kh, 32, 1.0f);
    proj_mma_kernel<128, 2, 4><<<dim3(HW / 128, 2, Bn), 256, SM_V >>>(p_x2h, p_Wv, v_b, p_Vh, 256, 1.0f);

    // flash attention + residual
    flash_mma_kernel<<<dim3(HW / BM, Bn), NTHR, FLASH_SMEM>>>(p_Qh, p_Kh, p_Vh, x1, p_g1, gamma, out);
}

// round 11
// speedup vs baseline: 1.0709x; 1.0709x over previous
#include <cuda_runtime.h>
#include <cuda_fp16.h>
#include <math.h>
#include <cstdint>

// Problem constants
#define Bn  4
#define Cc  256
#define C8  32
#define HH  64
#define WW  64
#define HW  4096
#define CHW (Cc*HW)
#define TOT (Bn*CHW)

// ---------------- scratch (__device__ globals) ------------------------------
__device__ float g_mean1[Bn*HW];
__device__ float g_max1 [Bn*HW];
__device__ float g_mean2[Bn*HW];
__device__ float g_max2 [Bn*HW];
__device__ float g_gate1[Bn*HW];
__device__ float g_gate2[Bn*HW];
__device__ __align__(16) __half g_x1h[(size_t)Bn*CHW];     // [B][C][HW] fp16 gated x1
__device__ __align__(16) __half g_x2h[(size_t)Bn*CHW];     // [B][C][HW] fp16 gated x2
__device__ __align__(16) __half g_Wq[C8*Cc];
__device__ __align__(16) __half g_Wk[C8*Cc];
__device__ __align__(16) __half g_Wv[Cc*Cc];
__device__ __align__(128) __half g_Qh[(size_t)Bn*HW*32];   // [B][N][32]  (pre-scaled by log2e)
__device__ __align__(128) __half g_Kh[(size_t)Bn*HW*32];   // [B][N][32]
__device__ __align__(128) __half g_Vh[(size_t)Bn*HW*256];  // [B][N][256]

// ======================= warp MMA helpers ====================================
__device__ __forceinline__ uint32_t smem_to_u32(const void* p) {
    uint32_t a;
    asm("{ .reg .u64 t; cvta.to.shared.u64 t, %1; cvt.u32.u64 %0, t; }" : "=r"(a) : "l"(p));
    return a;
}
__device__ __forceinline__ void mma16816(float* d, const uint32_t* a, const uint32_t* b) {
    asm volatile("mma.sync.aligned.m16n8k16.row.col.f32.f16.f16.f32 "
                 "{%0,%1,%2,%3}, {%4,%5,%6,%7}, {%8,%9}, {%0,%1,%2,%3};"
                 : "+f"(d[0]), "+f"(d[1]), "+f"(d[2]), "+f"(d[3])
                 : "r"(a[0]), "r"(a[1]), "r"(a[2]), "r"(a[3]), "r"(b[0]), "r"(b[1]));
}
__device__ __forceinline__ void ldsm4(uint32_t* r, uint32_t addr) {
    asm volatile("ldmatrix.sync.aligned.m8n8.x4.shared.b16 {%0,%1,%2,%3}, [%4];"
                 : "=r"(r[0]), "=r"(r[1]), "=r"(r[2]), "=r"(r[3]) : "r"(addr));
}
__device__ __forceinline__ void ldsm4t(uint32_t* r, uint32_t addr) {
    asm volatile("ldmatrix.sync.aligned.m8n8.x4.trans.shared.b16 {%0,%1,%2,%3}, [%4];"
                 : "=r"(r[0]), "=r"(r[1]), "=r"(r[2]), "=r"(r[3]) : "r"(addr));
}
__device__ __forceinline__ void cpa16(uint32_t dst, const void* src) {
    asm volatile("cp.async.cg.shared.global [%0], [%1], 16;" :: "r"(dst), "l"(src) : "memory");
}
#define CP_COMMIT() asm volatile("cp.async.commit_group;" ::: "memory")
#define CP_WAIT0()  asm volatile("cp.async.wait_group 0;" ::: "memory")
#define CP_WAIT1()  asm volatile("cp.async.wait_group 1;" ::: "memory")

__device__ __forceinline__ uint32_t packh2(float a, float b) {
    __half2 h = __float22half2_rn(make_float2(a, b));
    return *reinterpret_cast<uint32_t*>(&h);
}

// ---------------- kernel 1: channel mean & max (both inputs, z-merged) -------
__global__ __launch_bounds__(256) void reduce_kernel(const float* __restrict__ xa,
                                                     const float* __restrict__ xb,
                                                     float* __restrict__ meanA, float* __restrict__ maxA,
                                                     float* __restrict__ meanB, float* __restrict__ maxB) {
    __shared__ float S[4][64], M[4][64];
    const float* x = blockIdx.z ? xb : xa;
    float* meanO = blockIdx.z ? meanB : meanA;
    float* maxO  = blockIdx.z ? maxB  : maxA;
    int nl = threadIdx.x & 63, cg = threadIdx.x >> 6;
    int n = blockIdx.x * 64 + nl;
    int b = blockIdx.y;
    const float* xp = x + (size_t)b * CHW + (size_t)cg * 64 * HW + n;
    float s = 0.f, m = -3.4e38f;
#pragma unroll 8
    for (int i = 0; i < 64; ++i) { float v = xp[(size_t)i * HW]; s += v; m = fmaxf(m, v); }
    S[cg][nl] = s; M[cg][nl] = m;
    __syncthreads();
    if (cg == 0) {
        s = S[0][nl] + S[1][nl] + S[2][nl] + S[3][nl];
        m = fmaxf(fmaxf(M[0][nl], M[1][nl]), fmaxf(M[2][nl], M[3][nl]));
        meanO[b * HW + n] = s * (1.0f / Cc);
        maxO [b * HW + n] = m;
    }
}

// ---------------- kernel 2: 3x3 conv + sigmoid -> gates (z-merged) -----------
__global__ void gate_kernel(const float* __restrict__ meanA, const float* __restrict__ maxA,
                            const float* __restrict__ meanB, const float* __restrict__ maxB,
                            const float* __restrict__ w,
                            float* __restrict__ gateA, float* __restrict__ gateB) {
    const float* meanI = blockIdx.z ? meanB : meanA;
    const float* maxI  = blockIdx.z ? maxB  : maxA;
    float* gate = blockIdx.z ? gateB : gateA;
    int n = blockIdx.x * 256 + threadIdx.x;
    int b = blockIdx.y;
    int h = n >> 6, ww2 = n & 63;
    float a = 0.f;
#pragma unroll
    for (int dh = -1; dh <= 1; ++dh) {
        int hh = h + dh; if (hh < 0 || hh >= HH) continue;
#pragma unroll
        for (int dw = -1; dw <= 1; ++dw) {
            int wv = ww2 + dw; if (wv < 0 || wv >= WW) continue;
            int idx = b * HW + hh * WW + wv;
            int kid = (dh + 1) * 3 + (dw + 1);
            a += meanI[idx] * __ldg(&w[kid]) + maxI[idx] * __ldg(&w[9 + kid]);
        }
    }
    gate[b * HW + n] = 1.f / (1.f + __expf(-a));
}

// ---------------- kernel 3: weight fp32 -> fp16 conversion -------------------
__global__ void wcvt_kernel(const float* __restrict__ qw, const float* __restrict__ kw,
                            const float* __restrict__ vw,
                            __half* __restrict__ whq, __half* __restrict__ whk,
                            __half* __restrict__ whv) {
    int i = blockIdx.x * 256 + threadIdx.x;
    if (i < 8192)        whq[i] = __float2half(qw[i]);
    else if (i < 16384)  whk[i - 8192] = __float2half(kw[i - 8192]);
    else                 whv[i - 16384] = __float2half(vw[i - 16384]);
}

// ---------------- kernel 4a: x1h = fp16(x1 * gate1) --------------------------
__global__ __launch_bounds__(256) void ew_x1_kernel(const float* __restrict__ x,
                                                    const float* __restrict__ gate,
                                                    __half* __restrict__ xh) {
    int idx = (blockIdx.x * 256 + threadIdx.x) * 4;
    int b = blockIdx.y;
    int n = idx & (HW - 1);
    float4 xv = *(const float4*)&x[(size_t)b * CHW + idx];
    float4 gv = *(const float4*)&gate[b * HW + n];
    uint2 o;
    o.x = packh2(xv.x * gv.x, xv.y * gv.y);
    o.y = packh2(xv.z * gv.z, xv.w * gv.w);
    *(uint2*)&xh[(size_t)b * CHW + idx] = o;
}

// ---------------- kernel 4b: x2s (fp32 out) + x2h (fp16) ---------------------
__global__ __launch_bounds__(256) void ew_x2_kernel(const float* __restrict__ x,
                                                    const float* __restrict__ gate,
                                                    __half* __restrict__ xh,
                                                    float* __restrict__ xs) {
    int idx = (blockIdx.x * 256 + threadIdx.x) * 4;
    int b = blockIdx.y;
    int n = idx & (HW - 1);
    float4 xv = *(const float4*)&x[(size_t)b * CHW + idx];
    float4 gv = *(const float4*)&gate[b * HW + n];
    float4 r = make_float4(xv.x * gv.x, xv.y * gv.y, xv.z * gv.z, xv.w * gv.w);
    *(float4*)&xs[(size_t)b * CHW + idx] = r;
    uint2 o;
    o.x = packh2(r.x, r.y);
    o.y = packh2(r.z, r.w);
    *(uint2*)&xh[(size_t)b * CHW + idx] = o;
}

// ---------------- kernel 5: mma projection -----------------------------------
#define XBUF  (32 * 136 * 2)             // 8704 bytes per X stage
#define XSTG  (2 * XBUF)                 // 17408

template<int OT, int WMG, int MT>
__global__ __launch_bounds__(256) void proj_mma_kernel(const __half* __restrict__ Xg,
                                                       const __half* __restrict__ Wg,
                                                       const float* __restrict__ bias,
                                                       __half* __restrict__ out,
                                                       int Ototal, float scale) {
    extern __shared__ char smem[];
    __half* Wsm = (__half*)(smem + XSTG);            // [OT][264]
    uint32_t sb = smem_to_u32(smem);

    int t = threadIdx.x, lane = t & 31, w = t >> 5;
    int gr = lane >> 2, gc = lane & 3;
    int n0 = blockIdx.x * 128;
    int o0g = blockIdx.y * OT;
    int b = blockIdx.z;
    int wm0 = (w % WMG) * (MT * 16);
    int wo0 = (w / WMG) * 32;

    const __half* Xb = Xg + (size_t)b * CHW + n0;

#pragma unroll
    for (int it = 0; it < OT / 8; ++it) {
        int lin = it * 256 + t;
        int row = lin >> 5, ch = lin & 31;
        *(uint4*)&Wsm[row * 264 + ch * 8] = *(const uint4*)&Wg[(size_t)(o0g + row) * Cc + ch * 8];
    }

    auto loadX = [&](int ks) {
        const __half* src = Xb + (size_t)(ks * 32) * HW;
        uint32_t dstb = sb + (ks & 1) * XBUF;
#pragma unroll
        for (int it = 0; it < 2; ++it) {
            int lin = it * 256 + t;
            int row = lin >> 4, ch = lin & 15;
            cpa16(dstb + (row * 136 + ch * 8) * 2, src + (size_t)row * HW + ch * 8);
        }
    };

    loadX(0); CP_COMMIT();

    float oacc[MT][4][4];
#pragma unroll
    for (int mt = 0; mt < MT; ++mt)
#pragma unroll
        for (int nt = 0; nt < 4; ++nt)
#pragma unroll
            for (int j = 0; j < 4; ++j) oacc[mt][nt][j] = 0.f;

    for (int ks = 0; ks < 8; ++ks) {
        if (ks < 7) { loadX(ks + 1); CP_COMMIT(); CP_WAIT1(); }
        else        { CP_WAIT0(); }
        __syncthreads();

        uint32_t xbuf = sb + (ks & 1) * XBUF;
#pragma unroll
        for (int kt = 0; kt < 2; ++kt) {
            uint32_t af[MT][4];
#pragma unroll
            for (int mt = 0; mt < MT; ++mt) {
                uint32_t r[4];
                uint32_t addr = xbuf + ((kt * 16 + (lane & 15)) * 136
                                        + wm0 + mt * 16 + ((lane >> 4) << 3)) * 2;
                ldsm4t(r, addr);
                af[mt][0] = r[0]; af[mt][1] = r[2]; af[mt][2] = r[1]; af[mt][3] = r[3];
            }
            int ksk = ks * 32 + kt * 16;
#pragma unroll
            for (int nt = 0; nt < 4; ++nt) {
                uint32_t bf[2];
                bf[0] = *(const uint32_t*)&Wsm[(wo0 + nt * 8 + gr) * 264 + ksk + 2 * gc];
                bf[1] = *(const uint32_t*)&Wsm[(wo0 + nt * 8 + gr) * 264 + ksk + 8 + 2 * gc];
#pragma unroll
                for (int mt = 0; mt < MT; ++mt)
                    mma16816(oacc[mt][nt], af[mt], bf);
            }
        }
        __syncthreads();
    }

    uint32_t* outp = (uint32_t*)out;
    int ostr = Ototal >> 1;
#pragma unroll
    for (int nt = 0; nt < 4; ++nt) {
        int o = o0g + wo0 + nt * 8 + 2 * gc;
        float blo = __ldg(&bias[o]), bhi = __ldg(&bias[o + 1]);
#pragma unroll
        for (int mt = 0; mt < MT; ++mt) {
            int n = n0 + wm0 + mt * 16 + gr;
            outp[((size_t)b * HW + n)     * ostr + (o >> 1)]
                = packh2((oacc[mt][nt][0] + blo) * scale, (oacc[mt][nt][1] + bhi) * scale);
            outp[((size_t)b * HW + n + 8) * ostr + (o >> 1)]
                = packh2((oacc[mt][nt][2] + blo) * scale, (oacc[mt][nt][3] + bhi) * scale);
        }
    }
}

// ---------------- kernel 6: mma.sync fp16 flash attention + residual ---------
// BM=128 q/CTA, 512 thr = 16 warps = 8 qgroups x 2 chgroups.
// S + softmax computed ONLY by cg=0 warps; P fragments shared via SMEM.
// 3-stage cp.async pipeline; fp32 accumulators; exp2 softmax.
#define BM 128
#define BN 64
#define NTHR 512
#define NIT (HW / BN)
#define VSTR 264                       // halves per V row
#define VBYT (BN * VSTR * 2)           // 33792
#define KSTR 40                        // halves per K row (64B + 16B pad)
#define KBYT (BN * KSTR * 2)           // 5120
#define SSTR (VBYT + KBYT)             // 38912 per stage
#define PFOFF (3 * SSTR)               // 116736: P-fragment exchange, 16 KB
#define SCOFF (PFOFF + 16384)          // 133120: per-qg rescale factors, 64 B
#define LSOFF (SCOFF + 64)             // 133184: per-row lsum, 512 B
#define FLASH_SMEM 133760              // >= LSOFF+512 and >= epilogue 131584

__global__ __launch_bounds__(NTHR, 1) void flash_mma_kernel(
    const __half* __restrict__ Qg, const __half* __restrict__ Kg,
    const __half* __restrict__ Vg,
    const float* __restrict__ x1, const float* __restrict__ gate1,
    const float* __restrict__ gamma,
    float* __restrict__ out) {
    extern __shared__ char smem[];
    uint32_t sbase = smem_to_u32(smem);
    float* Os = (float*)smem;                        // epilogue staging [128][257]
    uint2* Pf = (uint2*)(smem + PFOFF);              // [8 qg][8 j][32 lane]
    float2* Sc = (float2*)(smem + SCOFF);            // [8 qg]
    float* Ls = (float*)(smem + LSOFF);              // [128 rows]

    int t = threadIdx.x, lane = t & 31, w = t >> 5;
    int qg = w & 7, cg = w >> 3;
    int b = blockIdx.y, m0 = blockIdx.x * BM;
    int r = lane >> 2, c2 = (lane & 3) * 2;

    const __half* Qb = Qg + ((size_t)b * HW + m0 + qg * 16) * 32;
    const __half* Kb = Kg + (size_t)b * HW * 32;
    const __half* Vb = Vg + (size_t)b * HW * 256;

    // Q fragments (only used by cg==0, but cheap to load uniformly)
    uint32_t qf[2][4];
#pragma unroll
    for (int kt = 0; kt < 2; ++kt) {
        qf[kt][0] = *(const uint32_t*)&Qb[(r)     * 32 + kt * 16 + c2];
        qf[kt][1] = *(const uint32_t*)&Qb[(r + 8) * 32 + kt * 16 + c2];
        qf[kt][2] = *(const uint32_t*)&Qb[(r)     * 32 + kt * 16 + 8 + c2];
        qf[kt][3] = *(const uint32_t*)&Qb[(r + 8) * 32 + kt * 16 + 8 + c2];
    }

    // stage loader: V (64 keys x 256ch) + K (64 keys x 32ch)
    auto loadStage = [&](int s) {
        uint32_t base = sbase + (s % 3) * SSTR;
        const __half* vsrc = Vb + (size_t)s * BN * 256;
#pragma unroll
        for (int it = 0; it < 4; ++it) {
            int lin = it * NTHR + t;
            int key = lin >> 5, ch16 = lin & 31;
            cpa16(base + key * (VSTR * 2) + ch16 * 16, vsrc + (size_t)key * 256 + ch16 * 8);
        }
        if (t < 256) {
            int row = t >> 2, ch16 = t & 3;
            cpa16(base + VBYT + row * (KSTR * 2) + ch16 * 16,
                  Kb + ((size_t)s * BN + row) * 32 + ch16 * 8);
        }
    };

    float oacc[16][4];
#pragma unroll
    for (int i = 0; i < 16; ++i)
#pragma unroll
        for (int j = 0; j < 4; ++j) oacc[i][j] = 0.f;
    float mrow0 = -3.4e38f, mrow1 = -3.4e38f, lsum0 = 0.f, lsum1 = 0.f;

    loadStage(0); CP_COMMIT();
    loadStage(1); CP_COMMIT();

    int t2 = lane >> 3, rw = lane & 7;   // ldsm K addressing
    for (int i = 0; i < NIT; ++i) {
        if (i < NIT - 2) CP_WAIT1(); else CP_WAIT0();
        __syncthreads();
        if (i + 2 < NIT) { loadStage(i + 2); CP_COMMIT(); }

        uint32_t stg = sbase + (i % 3) * SSTR;

        uint32_t pf[4][4];
        if (cg == 0) {
            uint32_t kb = stg + VBYT;
            // ---- S = Q K^T : 16 q rows x 64 keys, K via ldmatrix.x4 ----
            float sacc[8][4];
#pragma unroll
            for (int nt = 0; nt < 8; ++nt)
#pragma unroll
                for (int j = 0; j < 4; ++j) sacc[nt][j] = 0.f;
#pragma unroll
            for (int kt = 0; kt < 2; ++kt) {
#pragma unroll
                for (int j4 = 0; j4 < 4; ++j4) {
                    uint32_t kf[4];
                    uint32_t addr = kb + ((j4 * 16 + (t2 >> 1) * 8 + rw) * KSTR
                                          + kt * 16 + (t2 & 1) * 8) * 2;
                    ldsm4(kf, addr);
                    mma16816(sacc[2 * j4],     qf[kt], kf);
                    mma16816(sacc[2 * j4 + 1], qf[kt], kf + 2);
                }
            }

            // ---- online softmax (base-2; Q pre-scaled by log2e) ----
            float tm0 = -3.4e38f, tm1 = -3.4e38f;
#pragma unroll
            for (int nt = 0; nt < 8; ++nt) {
                tm0 = fmaxf(tm0, fmaxf(sacc[nt][0], sacc[nt][1]));
                tm1 = fmaxf(tm1, fmaxf(sacc[nt][2], sacc[nt][3]));
            }
            tm0 = fmaxf(tm0, __shfl_xor_sync(0xffffffffu, tm0, 1));
            tm0 = fmaxf(tm0, __shfl_xor_sync(0xffffffffu, tm0, 2));
            tm1 = fmaxf(tm1, __shfl_xor_sync(0xffffffffu, tm1, 1));
            tm1 = fmaxf(tm1, __shfl_xor_sync(0xffffffffu, tm1, 2));
            float mn0 = fmaxf(mrow0, tm0), mn1 = fmaxf(mrow1, tm1);
            float sc0 = exp2f(mrow0 - mn0), sc1 = exp2f(mrow1 - mn1);
            mrow0 = mn0; mrow1 = mn1;

            float rs0 = 0.f, rs1 = 0.f;
#pragma unroll
            for (int nt = 0; nt < 8; ++nt) {
                float e0 = exp2f(sacc[nt][0] - mn0);
                float e1 = exp2f(sacc[nt][1] - mn0);
                float e2 = exp2f(sacc[nt][2] - mn1);
                float e3 = exp2f(sacc[nt][3] - mn1);
                rs0 += e0 + e1; rs1 += e2 + e3;
                pf[nt >> 1][(nt & 1) * 2 + 0] = packh2(e0, e1);
                pf[nt >> 1][(nt & 1) * 2 + 1] = packh2(e2, e3);
            }
            rs0 += __shfl_xor_sync(0xffffffffu, rs0, 1);
            rs0 += __shfl_xor_sync(0xffffffffu, rs0, 2);
            rs1 += __shfl_xor_sync(0xffffffffu, rs1, 1);
            rs1 += __shfl_xor_sync(0xffffffffu, rs1, 2);
            lsum0 = lsum0 * sc0 + rs0;
            lsum1 = lsum1 * sc1 + rs1;

            // publish P fragments + rescale factors
            uint32_t* pfa = (uint32_t*)pf;
#pragma unroll
            for (int j = 0; j < 8; ++j)
                Pf[qg * 256 + j * 32 + lane] = make_uint2(pfa[2 * j], pfa[2 * j + 1]);
            if (lane == 0) Sc[qg] = make_float2(sc0, sc1);
        }
        __syncthreads();

        // all warps: fetch rescale factors (cg1 also fetches P fragments)
        float2 scv = Sc[qg];
        if (cg == 1) {
            uint32_t* pfa = (uint32_t*)pf;
#pragma unroll
            for (int j = 0; j < 8; ++j) {
                uint2 v = Pf[qg * 256 + j * 32 + lane];
                pfa[2 * j] = v.x; pfa[2 * j + 1] = v.y;
            }
        }
        if (scv.x < 1.f || scv.y < 1.f) {
#pragma unroll
            for (int ct = 0; ct < 16; ++ct) {
                oacc[ct][0] *= scv.x; oacc[ct][1] *= scv.x;
                oacc[ct][2] *= scv.y; oacc[ct][3] *= scv.y;
            }
        }

        // ---- O += P V : 128 channels for this warp ----
        uint32_t rowoff = (lane & 15) * (VSTR * 2) + ((lane >> 4) * 8 + cg * 128) * 2;
#pragma unroll
        for (int kt2 = 0; kt2 < 4; ++kt2) {
            uint32_t base = stg + kt2 * 16 * (VSTR * 2) + rowoff;
#pragma unroll
            for (int cp = 0; cp < 8; ++cp) {
                uint32_t vf[4];
                ldsm4t(vf, base + cp * 32);
                mma16816(oacc[2 * cp],     pf[kt2], vf);
                mma16816(oacc[2 * cp + 1], pf[kt2], vf + 2);
            }
        }
    }

    // ---- publish row sums, then epilogue ----
    if (cg == 0 && (lane & 3) == 0) {
        Ls[qg * 16 + r] = lsum0;
        Ls[qg * 16 + r + 8] = lsum1;
    }
    __syncthreads();
    float inv0 = 1.0f / Ls[qg * 16 + r];
    float inv1 = 1.0f / Ls[qg * 16 + r + 8];
    int row = qg * 16 + r;
#pragma unroll
    for (int ct = 0; ct < 16; ++ct) {
        int ch = cg * 128 + ct * 8 + c2;
        Os[row * 257 + ch]           = oacc[ct][0] * inv0;
        Os[row * 257 + ch + 1]       = oacc[ct][1] * inv0;
        Os[(row + 8) * 257 + ch]     = oacc[ct][2] * inv1;
        Os[(row + 8) * 257 + ch + 1] = oacc[ct][3] * inv1;
    }
    __syncthreads();

    float g = __ldg(gamma);
    int nloc = t & 127, cquad = t >> 7;
    float gg = gate1[b * HW + m0 + nloc];
#pragma unroll 4
    for (int it = 0; it < 64; ++it) {
        int ch = it * 4 + cquad;
        size_t gi = (size_t)b * CHW + (size_t)ch * HW + m0 + nloc;
        out[gi] = g * Os[nloc * 257 + ch] + x1[gi] * gg;
    }
}

// ---------------- launcher ---------------------------------------------------
extern "C" void kernel_launch(void* const* d_in, const int* in_sizes, int n_in,
                              void* d_out, int out_size) {
    const float* x1    = (const float*)d_in[0];
    const float* x2    = (const float*)d_in[1];
    const float* sa_w  = (const float*)d_in[2];
    const float* q_w   = (const float*)d_in[3];
    const float* q_b   = (const float*)d_in[4];
    const float* k_w   = (const float*)d_in[5];
    const float* k_b   = (const float*)d_in[6];
    const float* v_w   = (const float*)d_in[7];
    const float* v_b   = (const float*)d_in[8];
    const float* gamma = (const float*)d_in[9];

    float* out = (float*)d_out;        // out1 at [0, TOT), x2s at [TOT, 2*TOT)
    float* x2s = out + TOT;

    float *p_m1, *p_x1m, *p_m2, *p_x2m, *p_g1, *p_g2;
    __half *p_x1h, *p_x2h, *p_Wq, *p_Wk, *p_Wv, *p_Qh, *p_Kh, *p_Vh;
    cudaGetSymbolAddress((void**)&p_m1,  g_mean1);
    cudaGetSymbolAddress((void**)&p_x1m, g_max1);
    cudaGetSymbolAddress((void**)&p_m2,  g_mean2);
    cudaGetSymbolAddress((void**)&p_x2m, g_max2);
    cudaGetSymbolAddress((void**)&p_g1,  g_gate1);
    cudaGetSymbolAddress((void**)&p_g2,  g_gate2);
    cudaGetSymbolAddress((void**)&p_x1h, g_x1h);
    cudaGetSymbolAddress((void**)&p_x2h, g_x2h);
    cudaGetSymbolAddress((void**)&p_Wq,  g_Wq);
    cudaGetSymbolAddress((void**)&p_Wk,  g_Wk);
    cudaGetSymbolAddress((void**)&p_Wv,  g_Wv);
    cudaGetSymbolAddress((void**)&p_Qh,  g_Qh);
    cudaGetSymbolAddress((void**)&p_Kh,  g_Kh);
    cudaGetSymbolAddress((void**)&p_Vh,  g_Vh);

    const int SM_QK = XSTG + 32 * 264 * 2;    // 34304
    const int SM_V  = XSTG + 128 * 264 * 2;   // 84992
    cudaFuncSetAttribute((const void*)proj_mma_kernel<32, 8, 1>,
                         cudaFuncAttributeMaxDynamicSharedMemorySize, SM_QK);
    cudaFuncSetAttribute((const void*)proj_mma_kernel<128, 2, 4>,
                         cudaFuncAttributeMaxDynamicSharedMemorySize, SM_V);
    cudaFuncSetAttribute(flash_mma_kernel, cudaFuncAttributeMaxDynamicSharedMemorySize, FLASH_SMEM);

    // spatial attention stats + gates (x1/x2 merged via grid.z)
    reduce_kernel<<<dim3(HW / 64, Bn, 2), 256>>>(x1, x2, p_m1, p_x1m, p_m2, p_x2m);
    gate_kernel<<<dim3(HW / 256, Bn, 2), 256>>>(p_m1, p_x1m, p_m2, p_x2m, sa_w, p_g1, p_g2);
    wcvt_kernel<<<320, 256>>>(q_w, k_w, v_w, p_Wq, p_Wk, p_Wv);

    // gated activations (x2s also to output)
    ew_x1_kernel<<<dim3(CHW / 1024, Bn), 256>>>(x1, p_g1, p_x1h);
    ew_x2_kernel<<<dim3(CHW / 1024, Bn), 256>>>(x2, p_g2, p_x2h, x2s);

    // projections (tensor core); Q pre-scaled by log2e for base-2 softmax
    const float LOG2E = 1.4426950408889634f;
    proj_mma_kernel<32, 8, 1><<<dim3(HW / 128, 1, Bn), 256, SM_QK>>>(p_x1h, p_Wq, q_b, p_Qh, 32, LOG2E);
    proj_mma_kernel<32, 8, 1><<<dim3(HW / 128, 1, Bn), 256, SM_QK>>>(p_x2h, p_Wk, k_b, p_Kh, 32, 1.0f);
    proj_mma_kernel<128, 2, 4><<<dim3(HW / 128, 2, Bn), 256, SM_V >>>(p_x2h, p_Wv, v_b, p_Vh, 256, 1.0f);

    // flash attention + residual
    flash_mma_kernel<<<dim3(HW / BM, Bn), NTHR, FLASH_SMEM>>>(p_Qh, p_Kh, p_Vh, x1, p_g1, gamma, out);
}

// round 12
// speedup vs baseline: 1.0793x; 1.0078x over previous
#include <cuda_runtime.h>
#include <cuda_fp16.h>
#include <math.h>
#include <cstdint>

// Problem constants
#define Bn  4
#define Cc  256
#define C8  32
#define HH  64
#define WW  64
#define HW  4096
#define CHW (Cc*HW)
#define TOT (Bn*CHW)

// ---------------- scratch (__device__ globals) ------------------------------
__device__ float g_mean1[Bn*HW];
__device__ float g_max1 [Bn*HW];
__device__ float g_mean2[Bn*HW];
__device__ float g_max2 [Bn*HW];
__device__ float g_gate1[Bn*HW];
__device__ float g_gate2[Bn*HW];
__device__ __align__(16) __half g_x1h[(size_t)Bn*CHW];     // [B][C][HW] fp16 gated x1
__device__ __align__(16) __half g_x2h[(size_t)Bn*CHW];     // [B][C][HW] fp16 gated x2
__device__ __align__(16) __half g_Wq[C8*Cc];
__device__ __align__(16) __half g_Wk[C8*Cc];
__device__ __align__(16) __half g_Wv[Cc*Cc];
__device__ __align__(128) __half g_Qh[(size_t)Bn*HW*32];   // [B][N][32]  (pre-scaled by log2e)
__device__ __align__(128) __half g_Kh[(size_t)Bn*HW*32];   // [B][N][32]
__device__ __align__(128) __half g_Vh[(size_t)Bn*HW*256];  // [B][N][256]

// ======================= warp MMA helpers ====================================
__device__ __forceinline__ uint32_t smem_to_u32(const void* p) {
    uint32_t a;
    asm("{ .reg .u64 t; cvta.to.shared.u64 t, %1; cvt.u32.u64 %0, t; }" : "=r"(a) : "l"(p));
    return a;
}
__device__ __forceinline__ void mma16816(float* d, const uint32_t* a, const uint32_t* b) {
    asm volatile("mma.sync.aligned.m16n8k16.row.col.f32.f16.f16.f32 "
                 "{%0,%1,%2,%3}, {%4,%5,%6,%7}, {%8,%9}, {%0,%1,%2,%3};"
                 : "+f"(d[0]), "+f"(d[1]), "+f"(d[2]), "+f"(d[3])
                 : "r"(a[0]), "r"(a[1]), "r"(a[2]), "r"(a[3]), "r"(b[0]), "r"(b[1]));
}
__device__ __forceinline__ void ldsm4(uint32_t* r, uint32_t addr) {
    asm volatile("ldmatrix.sync.aligned.m8n8.x4.shared.b16 {%0,%1,%2,%3}, [%4];"
                 : "=r"(r[0]), "=r"(r[1]), "=r"(r[2]), "=r"(r[3]) : "r"(addr));
}
__device__ __forceinline__ void ldsm4t(uint32_t* r, uint32_t addr) {
    asm volatile("ldmatrix.sync.aligned.m8n8.x4.trans.shared.b16 {%0,%1,%2,%3}, [%4];"
                 : "=r"(r[0]), "=r"(r[1]), "=r"(r[2]), "=r"(r[3]) : "r"(addr));
}
__device__ __forceinline__ void cpa16(uint32_t dst, const void* src) {
    asm volatile("cp.async.cg.shared.global [%0], [%1], 16;" :: "r"(dst), "l"(src) : "memory");
}
#define CP_COMMIT() asm volatile("cp.async.commit_group;" ::: "memory")
#define CP_WAIT0()  asm volatile("cp.async.wait_group 0;" ::: "memory")
#define CP_WAIT1()  asm volatile("cp.async.wait_group 1;" ::: "memory")

__device__ __forceinline__ uint32_t packh2(float a, float b) {
    __half2 h = __float22half2_rn(make_float2(a, b));
    return *reinterpret_cast<uint32_t*>(&h);
}

// ---------------- kernel 1: channel mean & max (both inputs, z-merged) -------
__global__ __launch_bounds__(256) void reduce_kernel(const float* __restrict__ xa,
                                                     const float* __restrict__ xb,
                                                     float* __restrict__ meanA, float* __restrict__ maxA,
                                                     float* __restrict__ meanB, float* __restrict__ maxB) {
    __shared__ float S[4][64], M[4][64];
    const float* x = blockIdx.z ? xb : xa;
    float* meanO = blockIdx.z ? meanB : meanA;
    float* maxO  = blockIdx.z ? maxB  : maxA;
    int nl = threadIdx.x & 63, cg = threadIdx.x >> 6;
    int n = blockIdx.x * 64 + nl;
    int b = blockIdx.y;
    const float* xp = x + (size_t)b * CHW + (size_t)cg * 64 * HW + n;
    float s = 0.f, m = -3.4e38f;
#pragma unroll 8
    for (int i = 0; i < 64; ++i) { float v = xp[(size_t)i * HW]; s += v; m = fmaxf(m, v); }
    S[cg][nl] = s; M[cg][nl] = m;
    __syncthreads();
    if (cg == 0) {
        s = S[0][nl] + S[1][nl] + S[2][nl] + S[3][nl];
        m = fmaxf(fmaxf(M[0][nl], M[1][nl]), fmaxf(M[2][nl], M[3][nl]));
        meanO[b * HW + n] = s * (1.0f / Cc);
        maxO [b * HW + n] = m;
    }
}

// ---------------- kernel 2: 3x3 conv + sigmoid -> gates (z-merged) -----------
__global__ void gate_kernel(const float* __restrict__ meanA, const float* __restrict__ maxA,
                            const float* __restrict__ meanB, const float* __restrict__ maxB,
                            const float* __restrict__ w,
                            float* __restrict__ gateA, float* __restrict__ gateB) {
    const float* meanI = blockIdx.z ? meanB : meanA;
    const float* maxI  = blockIdx.z ? maxB  : maxA;
    float* gate = blockIdx.z ? gateB : gateA;
    int n = blockIdx.x * 256 + threadIdx.x;
    int b = blockIdx.y;
    int h = n >> 6, ww2 = n & 63;
    float a = 0.f;
#pragma unroll
    for (int dh = -1; dh <= 1; ++dh) {
        int hh = h + dh; if (hh < 0 || hh >= HH) continue;
#pragma unroll
        for (int dw = -1; dw <= 1; ++dw) {
            int wv = ww2 + dw; if (wv < 0 || wv >= WW) continue;
            int idx = b * HW + hh * WW + wv;
            int kid = (dh + 1) * 3 + (dw + 1);
            a += meanI[idx] * __ldg(&w[kid]) + maxI[idx] * __ldg(&w[9 + kid]);
        }
    }
    gate[b * HW + n] = 1.f / (1.f + __expf(-a));
}

// ---------------- kernel 3: weight fp32 -> fp16 conversion -------------------
__global__ void wcvt_kernel(const float* __restrict__ qw, const float* __restrict__ kw,
                            const float* __restrict__ vw,
                            __half* __restrict__ whq, __half* __restrict__ whk,
                            __half* __restrict__ whv) {
    int i = blockIdx.x * 256 + threadIdx.x;
    if (i < 8192)        whq[i] = __float2half(qw[i]);
    else if (i < 16384)  whk[i - 8192] = __float2half(kw[i - 8192]);
    else                 whv[i - 16384] = __float2half(vw[i - 16384]);
}

// ---------------- kernel 4a: x1h = fp16(x1 * gate1) --------------------------
__global__ __launch_bounds__(256) void ew_x1_kernel(const float* __restrict__ x,
                                                    const float* __restrict__ gate,
                                                    __half* __restrict__ xh) {
    int idx = (blockIdx.x * 256 + threadIdx.x) * 4;
    int b = blockIdx.y;
    int n = idx & (HW - 1);
    float4 xv = *(const float4*)&x[(size_t)b * CHW + idx];
    float4 gv = *(const float4*)&gate[b * HW + n];
    uint2 o;
    o.x = packh2(xv.x * gv.x, xv.y * gv.y);
    o.y = packh2(xv.z * gv.z, xv.w * gv.w);
    *(uint2*)&xh[(size_t)b * CHW + idx] = o;
}

// ---------------- kernel 4b: x2s (fp32 out) + x2h (fp16) ---------------------
__global__ __launch_bounds__(256) void ew_x2_kernel(const float* __restrict__ x,
                                                    const float* __restrict__ gate,
                                                    __half* __restrict__ xh,
                                                    float* __restrict__ xs) {
    int idx = (blockIdx.x * 256 + threadIdx.x) * 4;
    int b = blockIdx.y;
    int n = idx & (HW - 1);
    float4 xv = *(const float4*)&x[(size_t)b * CHW + idx];
    float4 gv = *(const float4*)&gate[b * HW + n];
    float4 r = make_float4(xv.x * gv.x, xv.y * gv.y, xv.z * gv.z, xv.w * gv.w);
    *(float4*)&xs[(size_t)b * CHW + idx] = r;
    uint2 o;
    o.x = packh2(r.x, r.y);
    o.y = packh2(r.z, r.w);
    *(uint2*)&xh[(size_t)b * CHW + idx] = o;
}

// ---------------- kernel 5: mma projection -----------------------------------
#define XBUF  (32 * 136 * 2)             // 8704 bytes per X stage
#define XSTG  (2 * XBUF)                 // 17408

template<int OT, int WMG, int MT>
__global__ __launch_bounds__(256) void proj_mma_kernel(const __half* __restrict__ Xg,
                                                       const __half* __restrict__ Wg,
                                                       const float* __restrict__ bias,
                                                       __half* __restrict__ out,
                                                       int Ototal, float scale) {
    extern __shared__ char smem[];
    __half* Wsm = (__half*)(smem + XSTG);            // [OT][264]
    uint32_t sb = smem_to_u32(smem);

    int t = threadIdx.x, lane = t & 31, w = t >> 5;
    int gr = lane >> 2, gc = lane & 3;
    int n0 = blockIdx.x * 128;
    int o0g = blockIdx.y * OT;
    int b = blockIdx.z;
    int wm0 = (w % WMG) * (MT * 16);
    int wo0 = (w / WMG) * 32;

    const __half* Xb = Xg + (size_t)b * CHW + n0;

#pragma unroll
    for (int it = 0; it < OT / 8; ++it) {
        int lin = it * 256 + t;
        int row = lin >> 5, ch = lin & 31;
        *(uint4*)&Wsm[row * 264 + ch * 8] = *(const uint4*)&Wg[(size_t)(o0g + row) * Cc + ch * 8];
    }

    auto loadX = [&](int ks) {
        const __half* src = Xb + (size_t)(ks * 32) * HW;
        uint32_t dstb = sb + (ks & 1) * XBUF;
#pragma unroll
        for (int it = 0; it < 2; ++it) {
            int lin = it * 256 + t;
            int row = lin >> 4, ch = lin & 15;
            cpa16(dstb + (row * 136 + ch * 8) * 2, src + (size_t)row * HW + ch * 8);
        }
    };

    loadX(0); CP_COMMIT();

    float oacc[MT][4][4];
#pragma unroll
    for (int mt = 0; mt < MT; ++mt)
#pragma unroll
        for (int nt = 0; nt < 4; ++nt)
#pragma unroll
            for (int j = 0; j < 4; ++j) oacc[mt][nt][j] = 0.f;

    for (int ks = 0; ks < 8; ++ks) {
        if (ks < 7) { loadX(ks + 1); CP_COMMIT(); CP_WAIT1(); }
        else        { CP_WAIT0(); }
        __syncthreads();

        uint32_t xbuf = sb + (ks & 1) * XBUF;
#pragma unroll
        for (int kt = 0; kt < 2; ++kt) {
            uint32_t af[MT][4];
#pragma unroll
            for (int mt = 0; mt < MT; ++mt) {
                uint32_t r[4];
                uint32_t addr = xbuf + ((kt * 16 + (lane & 15)) * 136
                                        + wm0 + mt * 16 + ((lane >> 4) << 3)) * 2;
                ldsm4t(r, addr);
                af[mt][0] = r[0]; af[mt][1] = r[2]; af[mt][2] = r[1]; af[mt][3] = r[3];
            }
            int ksk = ks * 32 + kt * 16;
#pragma unroll
            for (int nt = 0; nt < 4; ++nt) {
                uint32_t bf[2];
                bf[0] = *(const uint32_t*)&Wsm[(wo0 + nt * 8 + gr) * 264 + ksk + 2 * gc];
                bf[1] = *(const uint32_t*)&Wsm[(wo0 + nt * 8 + gr) * 264 + ksk + 8 + 2 * gc];
#pragma unroll
                for (int mt = 0; mt < MT; ++mt)
                    mma16816(oacc[mt][nt], af[mt], bf);
            }
        }
        __syncthreads();
    }

    uint32_t* outp = (uint32_t*)out;
    int ostr = Ototal >> 1;
#pragma unroll
    for (int nt = 0; nt < 4; ++nt) {
        int o = o0g + wo0 + nt * 8 + 2 * gc;
        float blo = __ldg(&bias[o]), bhi = __ldg(&bias[o + 1]);
#pragma unroll
        for (int mt = 0; mt < MT; ++mt) {
            int n = n0 + wm0 + mt * 16 + gr;
            outp[((size_t)b * HW + n)     * ostr + (o >> 1)]
                = packh2((oacc[mt][nt][0] + blo) * scale, (oacc[mt][nt][1] + bhi) * scale);
            outp[((size_t)b * HW + n + 8) * ostr + (o >> 1)]
                = packh2((oacc[mt][nt][2] + blo) * scale, (oacc[mt][nt][3] + bhi) * scale);
        }
    }
}

// ---------------- kernel 6: mma.sync fp16 flash attention + residual ---------
// BM=128 q/CTA, 512 thr = 16 warps = 8 qgroups x 2 chgroups.
// S + softmax computed ONLY by cg=0 warps; P fragments shared via SMEM.
// 3-stage cp.async pipeline; fp32 accumulators; exp2 softmax.
#define BM 128
#define BN 64
#define NTHR 512
#define NIT (HW / BN)
#define VSTR 264                       // halves per V row
#define VBYT (BN * VSTR * 2)           // 33792
#define KSTR 40                        // halves per K row (64B + 16B pad)
#define KBYT (BN * KSTR * 2)           // 5120
#define SSTR (VBYT + KBYT)             // 38912 per stage
#define PFOFF (3 * SSTR)               // 116736: P-fragment exchange, 16 KB
#define SCOFF (PFOFF + 16384)          // 133120: per-qg rescale factors, 64 B
#define LSOFF (SCOFF + 64)             // 133184: per-row lsum, 512 B
#define FLASH_SMEM 133760              // >= LSOFF+512 and >= epilogue 131584

__global__ __launch_bounds__(NTHR, 1) void flash_mma_kernel(
    const __half* __restrict__ Qg, const __half* __restrict__ Kg,
    const __half* __restrict__ Vg,
    const float* __restrict__ x1, const float* __restrict__ gate1,
    const float* __restrict__ gamma,
    float* __restrict__ out) {
    extern __shared__ char smem[];
    uint32_t sbase = smem_to_u32(smem);
    float* Os = (float*)smem;                        // epilogue staging [128][257]
    uint2* Pf = (uint2*)(smem + PFOFF);              // [8 qg][8 j][32 lane]
    float2* Sc = (float2*)(smem + SCOFF);            // [8 qg]
    float* Ls = (float*)(smem + LSOFF);              // [128 rows]

    int t = threadIdx.x, lane = t & 31, w = t >> 5;
    int qg = w & 7, cg = w >> 3;
    int b = blockIdx.y, m0 = blockIdx.x * BM;
    int r = lane >> 2, c2 = (lane & 3) * 2;

    const __half* Qb = Qg + ((size_t)b * HW + m0 + qg * 16) * 32;
    const __half* Kb = Kg + (size_t)b * HW * 32;
    const __half* Vb = Vg + (size_t)b * HW * 256;

    // Q fragments (only used by cg==0, but cheap to load uniformly)
    uint32_t qf[2][4];
#pragma unroll
    for (int kt = 0; kt < 2; ++kt) {
        qf[kt][0] = *(const uint32_t*)&Qb[(r)     * 32 + kt * 16 + c2];
        qf[kt][1] = *(const uint32_t*)&Qb[(r + 8) * 32 + kt * 16 + c2];
        qf[kt][2] = *(const uint32_t*)&Qb[(r)     * 32 + kt * 16 + 8 + c2];
        qf[kt][3] = *(const uint32_t*)&Qb[(r + 8) * 32 + kt * 16 + 8 + c2];
    }

    // stage loader: V (64 keys x 256ch) + K (64 keys x 32ch)
    auto loadStage = [&](int s) {
        uint32_t base = sbase + (s % 3) * SSTR;
        const __half* vsrc = Vb + (size_t)s * BN * 256;
#pragma unroll
        for (int it = 0; it < 4; ++it) {
            int lin = it * NTHR + t;
            int key = lin >> 5, ch16 = lin & 31;
            cpa16(base + key * (VSTR * 2) + ch16 * 16, vsrc + (size_t)key * 256 + ch16 * 8);
        }
        if (t < 256) {
            int row = t >> 2, ch16 = t & 3;
            cpa16(base + VBYT + row * (KSTR * 2) + ch16 * 16,
                  Kb + ((size_t)s * BN + row) * 32 + ch16 * 8);
        }
    };

    float oacc[16][4];
#pragma unroll
    for (int i = 0; i < 16; ++i)
#pragma unroll
        for (int j = 0; j < 4; ++j) oacc[i][j] = 0.f;
    float mrow0 = -3.4e38f, mrow1 = -3.4e38f, lsum0 = 0.f, lsum1 = 0.f;

    loadStage(0); CP_COMMIT();
    loadStage(1); CP_COMMIT();

    int t2 = lane >> 3, rw = lane & 7;   // ldsm K addressing
    for (int i = 0; i < NIT; ++i) {
        if (i < NIT - 2) CP_WAIT1(); else CP_WAIT0();
        __syncthreads();
        if (i + 2 < NIT) { loadStage(i + 2); CP_COMMIT(); }

        uint32_t stg = sbase + (i % 3) * SSTR;

        uint32_t pf[4][4];
        if (cg == 0) {
            uint32_t kb = stg + VBYT;
            // ---- S = Q K^T : 16 q rows x 64 keys, K via ldmatrix.x4 ----
            float sacc[8][4];
#pragma unroll
            for (int nt = 0; nt < 8; ++nt)
#pragma unroll
                for (int j = 0; j < 4; ++j) sacc[nt][j] = 0.f;
#pragma unroll
            for (int kt = 0; kt < 2; ++kt) {
#pragma unroll
                for (int j4 = 0; j4 < 4; ++j4) {
                    uint32_t kf[4];
                    uint32_t addr = kb + ((j4 * 16 + (t2 >> 1) * 8 + rw) * KSTR
                                          + kt * 16 + (t2 & 1) * 8) * 2;
                    ldsm4(kf, addr);
                    mma16816(sacc[2 * j4],     qf[kt], kf);
                    mma16816(sacc[2 * j4 + 1], qf[kt], kf + 2);
                }
            }

            // ---- online softmax (base-2; Q pre-scaled by log2e) ----
            float tm0 = -3.4e38f, tm1 = -3.4e38f;
#pragma unroll
            for (int nt = 0; nt < 8; ++nt) {
                tm0 = fmaxf(tm0, fmaxf(sacc[nt][0], sacc[nt][1]));
                tm1 = fmaxf(tm1, fmaxf(sacc[nt][2], sacc[nt][3]));
            }
            tm0 = fmaxf(tm0, __shfl_xor_sync(0xffffffffu, tm0, 1));
            tm0 = fmaxf(tm0, __shfl_xor_sync(0xffffffffu, tm0, 2));
            tm1 = fmaxf(tm1, __shfl_xor_sync(0xffffffffu, tm1, 1));
            tm1 = fmaxf(tm1, __shfl_xor_sync(0xffffffffu, tm1, 2));
            float mn0 = fmaxf(mrow0, tm0), mn1 = fmaxf(mrow1, tm1);
            float sc0 = exp2f(mrow0 - mn0), sc1 = exp2f(mrow1 - mn1);
            mrow0 = mn0; mrow1 = mn1;

            float rs0 = 0.f, rs1 = 0.f;
#pragma unroll
            for (int nt = 0; nt < 8; ++nt) {
                float e0 = exp2f(sacc[nt][0] - mn0);
                float e1 = exp2f(sacc[nt][1] - mn0);
                float e2 = exp2f(sacc[nt][2] - mn1);
                float e3 = exp2f(sacc[nt][3] - mn1);
                rs0 += e0 + e1; rs1 += e2 + e3;
                pf[nt >> 1][(nt & 1) * 2 + 0] = packh2(e0, e1);
                pf[nt >> 1][(nt & 1) * 2 + 1] = packh2(e2, e3);
            }
            rs0 += __shfl_xor_sync(0xffffffffu, rs0, 1);
            rs0 += __shfl_xor_sync(0xffffffffu, rs0, 2);
            rs1 += __shfl_xor_sync(0xffffffffu, rs1, 1);
            rs1 += __shfl_xor_sync(0xffffffffu, rs1, 2);
            lsum0 = lsum0 * sc0 + rs0;
            lsum1 = lsum1 * sc1 + rs1;

            // publish P fragments + rescale factors
            uint32_t* pfa = (uint32_t*)pf;
#pragma unroll
            for (int j = 0; j < 8; ++j)
                Pf[qg * 256 + j * 32 + lane] = make_uint2(pfa[2 * j], pfa[2 * j + 1]);
            if (lane == 0) Sc[qg] = make_float2(sc0, sc1);
        }
        __syncthreads();

        // all warps: fetch rescale factors (cg1 also fetches P fragments)
        float2 scv = Sc[qg];
        if (cg == 1) {
            uint32_t* pfa = (uint32_t*)pf;
#pragma unroll
            for (int j = 0; j < 8; ++j) {
                uint2 v = Pf[qg * 256 + j * 32 + lane];
                pfa[2 * j] = v.x; pfa[2 * j + 1] = v.y;
            }
        }
        if (scv.x < 1.f || scv.y < 1.f) {
#pragma unroll
            for (int ct = 0; ct < 16; ++ct) {
                oacc[ct][0] *= scv.x; oacc[ct][1] *= scv.x;
                oacc[ct][2] *= scv.y; oacc[ct][3] *= scv.y;
            }
        }

        // ---- O += P V : 128 channels for this warp ----
        uint32_t rowoff = (lane & 15) * (VSTR * 2) + ((lane >> 4) * 8 + cg * 128) * 2;
#pragma unroll
        for (int kt2 = 0; kt2 < 4; ++kt2) {
            uint32_t base = stg + kt2 * 16 * (VSTR * 2) + rowoff;
#pragma unroll
            for (int cp = 0; cp < 8; ++cp) {
                uint32_t vf[4];
                ldsm4t(vf, base + cp * 32);
                mma16816(oacc[2 * cp],     pf[kt2], vf);
                mma16816(oacc[2 * cp + 1], pf[kt2], vf + 2);
            }
        }
    }

    // ---- publish row sums, then epilogue ----
    if (cg == 0 && (lane & 3) == 0) {
        Ls[qg * 16 + r] = lsum0;
        Ls[qg * 16 + r + 8] = lsum1;
    }
    __syncthreads();
    float inv0 = 1.0f / Ls[qg * 16 + r];
    float inv1 = 1.0f / Ls[qg * 16 + r + 8];
    int row = qg * 16 + r;
#pragma unroll
    for (int ct = 0; ct < 16; ++ct) {
        int ch = cg * 128 + ct * 8 + c2;
        Os[row * 257 + ch]           = oacc[ct][0] * inv0;
        Os[row * 257 + ch + 1]       = oacc[ct][1] * inv0;
        Os[(row + 8) * 257 + ch]     = oacc[ct][2] * inv1;
        Os[(row + 8) * 257 + ch + 1] = oacc[ct][3] * inv1;
    }
    __syncthreads();

    float g = __ldg(gamma);
    int nloc = t & 127, cquad = t >> 7;
    float gg = gate1[b * HW + m0 + nloc];
#pragma unroll 4
    for (int it = 0; it < 64; ++it) {
        int ch = it * 4 + cquad;
        size_t gi = (size_t)b * CHW + (size_t)ch * HW + m0 + nloc;
        out[gi] = g * Os[nloc * 257 + ch] + x1[gi] * gg;
    }
}

// ---------------- launcher ---------------------------------------------------
extern "C" void kernel_launch(void* const* d_in, const int* in_sizes, int n_in,
                              void* d_out, int out_size) {
    const float* x1    = (const float*)d_in[0];
    const float* x2    = (const float*)d_in[1];
    const float* sa_w  = (const float*)d_in[2];
    const float* q_w   = (const float*)d_in[3];
    const float* q_b   = (const float*)d_in[4];
    const float* k_w   = (const float*)d_in[5];
    const float* k_b   = (const float*)d_in[6];
    const float* v_w   = (const float*)d_in[7];
    const float* v_b   = (const float*)d_in[8];
    const float* gamma = (const float*)d_in[9];

    float* out = (float*)d_out;        // out1 at [0, TOT), x2s at [TOT, 2*TOT)
    float* x2s = out + TOT;

    float *p_m1, *p_x1m, *p_m2, *p_x2m, *p_g1, *p_g2;
    __half *p_x1h, *p_x2h, *p_Wq, *p_Wk, *p_Wv, *p_Qh, *p_Kh, *p_Vh;
    cudaGetSymbolAddress((void**)&p_m1,  g_mean1);
    cudaGetSymbolAddress((void**)&p_x1m, g_max1);
    cudaGetSymbolAddress((void**)&p_m2,  g_mean2);
    cudaGetSymbolAddress((void**)&p_x2m, g_max2);
    cudaGetSymbolAddress((void**)&p_g1,  g_gate1);
    cudaGetSymbolAddress((void**)&p_g2,  g_gate2);
    cudaGetSymbolAddress((void**)&p_x1h, g_x1h);
    cudaGetSymbolAddress((void**)&p_x2h, g_x2h);
    cudaGetSymbolAddress((void**)&p_Wq,  g_Wq);
    cudaGetSymbolAddress((void**)&p_Wk,  g_Wk);
    cudaGetSymbolAddress((void**)&p_Wv,  g_Wv);
    cudaGetSymbolAddress((void**)&p_Qh,  g_Qh);
    cudaGetSymbolAddress((void**)&p_Kh,  g_Kh);
    cudaGetSymbolAddress((void**)&p_Vh,  g_Vh);

    const int SM_QK = XSTG + 32 * 264 * 2;    // 34304
    const int SM_V  = XSTG + 128 * 264 * 2;   // 84992
    cudaFuncSetAttribute((const void*)proj_mma_kernel<32, 8, 1>,
                         cudaFuncAttributeMaxDynamicSharedMemorySize, SM_QK);
    cudaFuncSetAttribute((const void*)proj_mma_kernel<128, 2, 4>,
                         cudaFuncAttributeMaxDynamicSharedMemorySize, SM_V);
    cudaFuncSetAttribute(flash_mma_kernel, cudaFuncAttributeMaxDynamicSharedMemorySize, FLASH_SMEM);

    // spatial attention stats + gates (x1/x2 merged via grid.z)
    reduce_kernel<<<dim3(HW / 64, Bn, 2), 256>>>(x1, x2, p_m1, p_x1m, p_m2, p_x2m);
    gate_kernel<<<dim3(HW / 256, Bn, 2), 256>>>(p_m1, p_x1m, p_m2, p_x2m, sa_w, p_g1, p_g2);
    wcvt_kernel<<<320, 256>>>(q_w, k_w, v_w, p_Wq, p_Wk, p_Wv);

    // gated activations (x2s also to output)
    ew_x1_kernel<<<dim3(CHW / 1024, Bn), 256>>>(x1, p_g1, p_x1h);
    ew_x2_kernel<<<dim3(CHW / 1024, Bn), 256>>>(x2, p_g2, p_x2h, x2s);

    // projections (tensor core); Q pre-scaled by log2e for base-2 softmax
    const float LOG2E = 1.4426950408889634f;
    proj_mma_kernel<32, 8, 1><<<dim3(HW / 128, 1, Bn), 256, SM_QK>>>(p_x1h, p_Wq, q_b, p_Qh, 32, LOG2E);
    proj_mma_kernel<32, 8, 1><<<dim3(HW / 128, 1, Bn), 256, SM_QK>>>(p_x2h, p_Wk, k_b, p_Kh, 32, 1.0f);
    proj_mma_kernel<128, 2, 4><<<dim3(HW / 128, 2, Bn), 256, SM_V >>>(p_x2h, p_Wv, v_b, p_Vh, 256, 1.0f);

    // flash attention + residual
    flash_mma_kernel<<<dim3(HW / BM, Bn), NTHR, FLASH_SMEM>>>(p_Qh, p_Kh, p_Vh, x1, p_g1, gamma, out);
}